// round 7
// baseline (speedup 1.0000x reference)
#include <cuda_runtime.h>
#include <cuda_fp16.h>
#include <cstdint>
#include <cstddef>

// ============================================================================
// Problem sizes
// ============================================================================
#define BATCH 4
#define SEQ   8192
#define DIM   1024
#define MTOT  (BATCH*SEQ)      // 32768 rows
#define NTOT  (2*DIM)          // 2048 combined output cols (gate | cand)
#define CH_T  32               // scan chunk length
#define NCHK  (SEQ/CH_T)       // 256 chunks per (b,d) channel
#define DV    (DIM/4)          // 256 vec4 channel groups

// ============================================================================
// Scratch (static device arrays — no allocation allowed)
// ============================================================================
__device__ __half g_xh[(size_t)MTOT*DIM];           // 64 MB
__device__ __half g_wh[(size_t)NTOT*DIM];           // 4 MB  (Wg rows 0..1023, Wc rows 1024..2047)
__device__ __half g_gate[(size_t)MTOT*DIM];         // 64 MB
__device__ __half g_cand[(size_t)MTOT*DIM];         // 64 MB
__device__ float g_Ast[(size_t)BATCH*NCHK*DIM];     // 4 MB
__device__ float g_Hst[(size_t)BATCH*NCHK*DIM];     // 4 MB
__device__ float g_Pst[(size_t)BATCH*NCHK*DIM];     // 4 MB

// ============================================================================
// Helpers (non-'a' PTX only: cp.async, ldmatrix, mma.sync)
// ============================================================================
__device__ __forceinline__ uint32_t smem_u32(const void* p){
    uint32_t a;
    asm("{ .reg .u64 t; cvta.to.shared.u64 t, %1; cvt.u32.u64 %0, t; }" : "=r"(a) : "l"(p));
    return a;
}
__device__ __forceinline__ void cp16(uint32_t smem_addr, const void* gptr){
    asm volatile("cp.async.cg.shared.global [%0], [%1], 16;"
                 :: "r"(smem_addr), "l"(__cvta_generic_to_global(gptr)) : "memory");
}
#define CP_COMMIT()  asm volatile("cp.async.commit_group;" ::: "memory")
#define CP_WAIT(n)   asm volatile("cp.async.wait_group %0;" :: "n"(n) : "memory")

__device__ __forceinline__ void ldsm4(uint32_t* r, uint32_t addr){
    asm volatile("ldmatrix.sync.aligned.m8n8.x4.shared.b16 {%0,%1,%2,%3}, [%4];"
                 : "=r"(r[0]),"=r"(r[1]),"=r"(r[2]),"=r"(r[3]) : "r"(addr));
}
__device__ __forceinline__ void mma16816(float* d, const uint32_t* a, const uint32_t* b){
    asm volatile("mma.sync.aligned.m16n8k16.row.col.f32.f16.f16.f32 "
                 "{%0,%1,%2,%3}, {%4,%5,%6,%7}, {%8,%9}, {%0,%1,%2,%3};"
                 : "+f"(d[0]),"+f"(d[1]),"+f"(d[2]),"+f"(d[3])
                 : "r"(a[0]),"r"(a[1]),"r"(a[2]),"r"(a[3]), "r"(b[0]),"r"(b[1]));
}

__device__ __forceinline__ float sigmoid_f(float v){
    return 1.0f / (1.0f + __expf(-v));
}
__device__ __forceinline__ float tanh_f(float v){
    float a = fabsf(v);
    float e = __expf(-2.0f * a);
    float t = (1.0f - e) / (1.0f + e);
    return copysignf(t, v);
}

// ============================================================================
// No-op kernel: aligns ncu's skip-5 capture onto the GEMM launch
// ============================================================================
__global__ void noop_kernel(){}

// ============================================================================
// Kernel 1: convert x (fp32) -> fp16
// ============================================================================
__global__ void conv_x_kernel(const float* __restrict__ x){
    size_t i = ((size_t)blockIdx.x * blockDim.x + threadIdx.x) * 4;
    float4 v = *reinterpret_cast<const float4*>(x + i);
    __half2* ph = reinterpret_cast<__half2*>(g_xh + i);
    ph[0] = __floats2half2_rn(v.x, v.y);
    ph[1] = __floats2half2_rn(v.z, v.w);
}

// ============================================================================
// Kernel 2: convert [Wg;Wc] (fp32) -> fp16, concatenated rows
// ============================================================================
__global__ void conv_w_kernel(const float* __restrict__ Wg, const float* __restrict__ Wc){
    size_t i = ((size_t)blockIdx.x * blockDim.x + threadIdx.x) * 4;
    const size_t HALF = (size_t)DIM * DIM;
    float4 v = (i < HALF) ? *reinterpret_cast<const float4*>(Wg + i)
                          : *reinterpret_cast<const float4*>(Wc + (i - HALF));
    __half2* ph = reinterpret_cast<__half2*>(g_wh + i);
    ph[0] = __floats2half2_rn(v.x, v.y);
    ph[1] = __floats2half2_rn(v.z, v.w);
}

// ============================================================================
// Kernel 3: fused dual GEMM (mma.sync fp16, fp32 accum)
//   BM=128, BN=256, BK=32, 512 threads (16 warps), warp tile 64x32, 1 CTA/SM
// ============================================================================
#define BM 128
#define BN 256
#define BK 32
#define NSTAGE 6
#define KITER (DIM/BK)              // 32
#define ROWB 64                     // bytes per smem row (32 halves)
#define A_BYTES (BM*ROWB)           // 8192
#define B_BYTES (BN*ROWB)           // 16384
#define STAGE_BYTES (A_BYTES + B_BYTES)  // 24576
#define GEMM_SMEM (NSTAGE*STAGE_BYTES + 128)   // ~147.5 KB

__global__ void __launch_bounds__(512, 1)
gemm_kernel(const float* __restrict__ bg, const float* __restrict__ bc){
    extern __shared__ char smem[];
    const uint32_t tb = (smem_u32(smem) + 127u) & ~127u;   // 128B-aligned tile base
    const int tid = threadIdx.x;
    const int wid = tid >> 5;
    const int lid = tid & 31;
    const int wm = wid >> 3;           // 0..1  (64-row slabs)
    const int wn = wid & 7;            // 0..7  (32-col slabs)
    const int n0 = blockIdx.x * BN;
    const int m0 = blockIdx.y * BM;

    // ---- stage loader: A|B, SW64-swizzled 64B rows (512 threads)
    auto load_stage = [&](int kk, int s){
        const uint32_t st = tb + (uint32_t)s * STAGE_BYTES;
        const int k0 = kk * BK;
        {                                           // A: 512 16B-chunks
            int r = tid >> 2;
            int c8 = (tid & 3) * 8;
            uint32_t off = (uint32_t)(r * ROWB + c8 * 2);
            off ^= (off >> 3) & 0x30;               // SW64 swizzle
            cp16(st + off, g_xh + (size_t)(m0 + r) * DIM + k0 + c8);
        }
        #pragma unroll
        for (int i = 0; i < 2; i++){                // B: 1024 16B-chunks
            int idx = i * 512 + tid;
            int r = idx >> 2;
            int c8 = (idx & 3) * 8;
            uint32_t off = (uint32_t)(r * ROWB + c8 * 2);
            off ^= (off >> 3) & 0x30;
            cp16(st + A_BYTES + off, g_wh + (size_t)(n0 + r) * DIM + k0 + c8);
        }
        CP_COMMIT();
    };

    float acc[4][4][4];
    #pragma unroll
    for (int a = 0; a < 4; a++)
        #pragma unroll
        for (int b = 0; b < 4; b++)
            #pragma unroll
            for (int c = 0; c < 4; c++) acc[a][b][c] = 0.0f;

    #pragma unroll
    for (int s = 0; s < NSTAGE-1; s++) load_stage(s, s);

    for (int kk = 0; kk < KITER; kk++){
        CP_WAIT(NSTAGE-2);
        __syncthreads();

        if (kk + NSTAGE-1 < KITER) load_stage(kk + NSTAGE-1, (kk + NSTAGE-1) % NSTAGE);
        else CP_COMMIT();   // empty group keeps wait_group accounting exact

        const uint32_t st = tb + (uint32_t)(kk % NSTAGE) * STAGE_BYTES;

        #pragma unroll
        for (int ks = 0; ks < 2; ks++){         // two k16 steps per BK=32
            uint32_t af[4][4], bf[2][4];
            #pragma unroll
            for (int mt = 0; mt < 4; mt++){
                int row = wm*64 + mt*16 + (lid & 15);
                uint32_t off = (uint32_t)(row * ROWB + ks*32 + ((lid >> 4) << 4));
                off ^= (off >> 3) & 0x30;
                ldsm4(af[mt], st + off);
            }
            #pragma unroll
            for (int nt = 0; nt < 2; nt++){     // each x4 covers 16 n-cols
                int row = wn*32 + nt*16 + (lid & 7) + ((lid >> 4) & 1) * 8;
                uint32_t off = (uint32_t)(row * ROWB + ks*32 + ((lid >> 3) & 1) * 16);
                off ^= (off >> 3) & 0x30;
                ldsm4(bf[nt], st + A_BYTES + off);
            }
            #pragma unroll
            for (int mt = 0; mt < 4; mt++){
                #pragma unroll
                for (int ng = 0; ng < 4; ng++){
                    mma16816(acc[mt][ng], af[mt], &bf[ng >> 1][(ng & 1) * 2]);
                }
            }
        }
    }

    // ---- epilogue: bias + activation, fp16 stores (half2)
    const bool isgate = (n0 < DIM);
    const float* bias = isgate ? bg : bc;
    __half* outp = isgate ? g_gate : g_cand;
    const int nb = isgate ? n0 : (n0 - DIM);
    const int g = lid >> 2, t = lid & 3;

    #pragma unroll
    for (int mt = 0; mt < 4; mt++){
        #pragma unroll
        for (int ng = 0; ng < 4; ng++){
            int col = nb + wn*32 + ng*8 + t*2;
            float b0 = bias[col], b1 = bias[col + 1];
            int row0 = m0 + wm*64 + mt*16 + g;
            int row1 = row0 + 8;
            float v00 = acc[mt][ng][0] + b0, v01 = acc[mt][ng][1] + b1;
            float v10 = acc[mt][ng][2] + b0, v11 = acc[mt][ng][3] + b1;
            if (isgate){
                v00 = sigmoid_f(v00); v01 = sigmoid_f(v01);
                v10 = sigmoid_f(v10); v11 = sigmoid_f(v11);
            } else {
                v00 = tanh_f(v00); v01 = tanh_f(v01);
                v10 = tanh_f(v10); v11 = tanh_f(v11);
            }
            *reinterpret_cast<__half2*>(outp + (size_t)row0 * DIM + col) = __floats2half2_rn(v00, v01);
            *reinterpret_cast<__half2*>(outp + (size_t)row1 * DIM + col) = __floats2half2_rn(v10, v11);
        }
    }
}

// ============================================================================
// Kernels 4/5/6: chunked linear-recurrence scan  h_t = g_t*h_{t-1} + c_t
// Each thread handles 4 adjacent channels (8B fp16 loads).
// ============================================================================
__device__ __forceinline__ void load4h(float* f, const __half* p){
    uint2 u = *reinterpret_cast<const uint2*>(p);
    __half2 h0 = *reinterpret_cast<__half2*>(&u.x);
    __half2 h1 = *reinterpret_cast<__half2*>(&u.y);
    float2 a = __half22float2(h0), b = __half22float2(h1);
    f[0] = a.x; f[1] = a.y; f[2] = b.x; f[3] = b.y;
}

__global__ void scan_pass1(){
    int t = blockIdx.x * 256 + threadIdx.x;      // 262144 threads
    int d  = t & (DV - 1);                       // vec4 channel group
    int ch = (t >> 8) & (NCHK - 1);
    int b  = t >> 16;
    size_t base = ((size_t)b * SEQ + (size_t)ch * CH_T) * DIM + (size_t)d * 4;
    float A[4] = {1.f,1.f,1.f,1.f};
    float H[4] = {0.f,0.f,0.f,0.f};
    #pragma unroll 4
    for (int i = 0; i < CH_T; i++){
        float g[4], c[4];
        load4h(g, g_gate + base);
        load4h(c, g_cand + base);
        #pragma unroll
        for (int j = 0; j < 4; j++){
            A[j] *= g[j];
            H[j] = g[j]*H[j] + c[j];
        }
        base += DIM;
    }
    size_t sidx = ((size_t)b * NCHK + ch) * DV + d;
    reinterpret_cast<float4*>(g_Ast)[sidx] = make_float4(A[0],A[1],A[2],A[3]);
    reinterpret_cast<float4*>(g_Hst)[sidx] = make_float4(H[0],H[1],H[2],H[3]);
}

__global__ void scan_pass2(){
    int t = blockIdx.x * 256 + threadIdx.x;      // 1024 threads
    int d = t & (DV - 1);
    int b = t >> 8;
    float4 P = make_float4(0.f,0.f,0.f,0.f);
    #pragma unroll 4
    for (int k = 0; k < NCHK; k++){
        size_t s = ((size_t)b * NCHK + k) * DV + d;
        reinterpret_cast<float4*>(g_Pst)[s] = P;
        float4 A = reinterpret_cast<const float4*>(g_Ast)[s];
        float4 H = reinterpret_cast<const float4*>(g_Hst)[s];
        P.x = A.x*P.x + H.x; P.y = A.y*P.y + H.y;
        P.z = A.z*P.z + H.z; P.w = A.w*P.w + H.w;
    }
}

__global__ void scan_pass3(float* __restrict__ out){
    int t = blockIdx.x * 256 + threadIdx.x;      // 262144 threads
    int d  = t & (DV - 1);
    int ch = (t >> 8) & (NCHK - 1);
    int b  = t >> 16;
    size_t base = ((size_t)b * SEQ + (size_t)ch * CH_T) * DIM + (size_t)d * 4;
    size_t sidx = ((size_t)b * NCHK + ch) * DV + d;
    float4 hp = reinterpret_cast<const float4*>(g_Pst)[sidx];
    float h[4] = {hp.x, hp.y, hp.z, hp.w};
    #pragma unroll 4
    for (int i = 0; i < CH_T; i++){
        float g[4], c[4];
        load4h(g, g_gate + base);
        load4h(c, g_cand + base);
        #pragma unroll
        for (int j = 0; j < 4; j++)
            h[j] = g[j]*h[j] + c[j];
        *reinterpret_cast<float4*>(out + base) = make_float4(h[0],h[1],h[2],h[3]);
        base += DIM;
    }
}

// ============================================================================
// Launch
// ============================================================================
extern "C" void kernel_launch(void* const* d_in, const int* in_sizes, int n_in,
                              void* d_out, int out_size){
    (void)in_sizes; (void)n_in; (void)out_size;
    const float* x  = (const float*)d_in[0];
    const float* Wg = (const float*)d_in[1];
    const float* bg = (const float*)d_in[2];
    const float* Wc = (const float*)d_in[3];
    const float* bc = (const float*)d_in[4];
    float* out = (float*)d_out;

    cudaFuncSetAttribute(gemm_kernel, cudaFuncAttributeMaxDynamicSharedMemorySize, GEMM_SMEM);

    conv_x_kernel<<<(MTOT*(size_t)DIM)/4/256, 256>>>(x);              // launch 0
    conv_w_kernel<<<(NTOT*(size_t)DIM)/4/256, 256>>>(Wg, Wc);         // launch 1
    noop_kernel<<<1, 32>>>();                                         // launch 2
    noop_kernel<<<1, 32>>>();                                         // launch 3
    noop_kernel<<<1, 32>>>();                                         // launch 4
    gemm_kernel<<<dim3(NTOT/BN, MTOT/BM), 512, GEMM_SMEM>>>(bg, bc);  // launch 5 -> ncu target
    scan_pass1<<<(BATCH*NCHK*DV)/256, 256>>>();                       // 1024 blocks
    scan_pass2<<<(BATCH*DV)/256, 256>>>();                            // 4 blocks
    scan_pass3<<<(BATCH*NCHK*DV)/256, 256>>>(out);                    // 1024 blocks
}

// round 8
// speedup vs baseline: 1.2067x; 1.2067x over previous
#include <cuda_runtime.h>
#include <cuda_fp16.h>
#include <cstdint>
#include <cstddef>

// ============================================================================
// Problem sizes
// ============================================================================
#define BATCH 4
#define SEQ   8192
#define DIM   1024
#define MTOT  (BATCH*SEQ)      // 32768 rows
#define NTOT  (2*DIM)          // 2048 combined output cols (gate | cand)
#define CH_T  32               // scan chunk length
#define NCHK  (SEQ/CH_T)       // 256 chunks per (b,d) channel
#define DV    (DIM/4)          // 256 vec4 channel groups

// ============================================================================
// Scratch (static device arrays — no allocation allowed)
// ============================================================================
__device__ __half g_xh[(size_t)MTOT*DIM];           // 64 MB
__device__ __half g_wh[(size_t)NTOT*DIM];           // 4 MB  (Wg rows 0..1023, Wc rows 1024..2047)
__device__ __half g_gate[(size_t)MTOT*DIM];         // 64 MB
__device__ __half g_cand[(size_t)MTOT*DIM];         // 64 MB
__device__ float g_Ast[(size_t)BATCH*NCHK*DIM];     // 4 MB
__device__ float g_Hst[(size_t)BATCH*NCHK*DIM];     // 4 MB
__device__ float g_Pst[(size_t)BATCH*NCHK*DIM];     // 4 MB

// ============================================================================
// Helpers (non-'a' PTX only: cp.async, ldmatrix, mma.sync)
// ============================================================================
__device__ __forceinline__ uint32_t smem_u32(const void* p){
    uint32_t a;
    asm("{ .reg .u64 t; cvta.to.shared.u64 t, %1; cvt.u32.u64 %0, t; }" : "=r"(a) : "l"(p));
    return a;
}
__device__ __forceinline__ void cp16(uint32_t smem_addr, const void* gptr){
    asm volatile("cp.async.cg.shared.global [%0], [%1], 16;"
                 :: "r"(smem_addr), "l"(__cvta_generic_to_global(gptr)) : "memory");
}
#define CP_COMMIT()  asm volatile("cp.async.commit_group;" ::: "memory")
#define CP_WAIT(n)   asm volatile("cp.async.wait_group %0;" :: "n"(n) : "memory")

__device__ __forceinline__ void ldsm4(uint32_t* r, uint32_t addr){
    asm volatile("ldmatrix.sync.aligned.m8n8.x4.shared.b16 {%0,%1,%2,%3}, [%4];"
                 : "=r"(r[0]),"=r"(r[1]),"=r"(r[2]),"=r"(r[3]) : "r"(addr));
}
__device__ __forceinline__ void mma16816(float* d, const uint32_t* a, const uint32_t* b){
    asm volatile("mma.sync.aligned.m16n8k16.row.col.f32.f16.f16.f32 "
                 "{%0,%1,%2,%3}, {%4,%5,%6,%7}, {%8,%9}, {%0,%1,%2,%3};"
                 : "+f"(d[0]),"+f"(d[1]),"+f"(d[2]),"+f"(d[3])
                 : "r"(a[0]),"r"(a[1]),"r"(a[2]),"r"(a[3]), "r"(b[0]),"r"(b[1]));
}

__device__ __forceinline__ float sigmoid_f(float v){
    return 1.0f / (1.0f + __expf(-v));
}
__device__ __forceinline__ float tanh_f(float v){
    float a = fabsf(v);
    float e = __expf(-2.0f * a);
    float t = (1.0f - e) / (1.0f + e);
    return copysignf(t, v);
}

// ============================================================================
// No-op kernel: aligns ncu's skip-5 capture onto the GEMM launch
// (harness adds one pre-launch; gemm must be my launch index 4)
// ============================================================================
__global__ void noop_kernel(){}

// ============================================================================
// Kernel 1: convert x (fp32) -> fp16
// ============================================================================
__global__ void conv_x_kernel(const float* __restrict__ x){
    size_t i = ((size_t)blockIdx.x * blockDim.x + threadIdx.x) * 4;
    float4 v = *reinterpret_cast<const float4*>(x + i);
    __half2* ph = reinterpret_cast<__half2*>(g_xh + i);
    ph[0] = __floats2half2_rn(v.x, v.y);
    ph[1] = __floats2half2_rn(v.z, v.w);
}

// ============================================================================
// Kernel 2: convert [Wg;Wc] (fp32) -> fp16, concatenated rows
// ============================================================================
__global__ void conv_w_kernel(const float* __restrict__ Wg, const float* __restrict__ Wc){
    size_t i = ((size_t)blockIdx.x * blockDim.x + threadIdx.x) * 4;
    const size_t HALF = (size_t)DIM * DIM;
    float4 v = (i < HALF) ? *reinterpret_cast<const float4*>(Wg + i)
                          : *reinterpret_cast<const float4*>(Wc + (i - HALF));
    __half2* ph = reinterpret_cast<__half2*>(g_wh + i);
    ph[0] = __floats2half2_rn(v.x, v.y);
    ph[1] = __floats2half2_rn(v.z, v.w);
}

// ============================================================================
// Kernel 3: fused dual GEMM (mma.sync fp16, fp32 accum)
//   BM=128, BN=128, BK=64 (SW128 rows), 8 warps, warp tile 64x32, 2 CTA/SM
// ============================================================================
#define BM 128
#define BN 128
#define BK 64
#define NSTAGE 3
#define KITER (DIM/BK)              // 16
#define ROWB 128                    // bytes per smem row (64 halves)
#define TILE_BYTES (128*ROWB)       // 16384 per matrix per stage
#define STAGE_BYTES (2*TILE_BYTES)  // A|B = 32768
#define GEMM_SMEM (NSTAGE*STAGE_BYTES + 128)
#define SWZ(off) ((off) ^ (((off) >> 3) & 0x70))

__global__ void __launch_bounds__(256, 2)
gemm_kernel(const float* __restrict__ bg, const float* __restrict__ bc){
    extern __shared__ char smem[];
    const uint32_t tb = (smem_u32(smem) + 127u) & ~127u;   // 128B-aligned tile base
    const int tid = threadIdx.x;
    const int wid = tid >> 5;
    const int lid = tid & 31;
    const int wm = wid >> 2;           // 0..1  (64-row slabs)
    const int wn = wid & 3;            // 0..3  (32-col slabs)
    const int n0 = blockIdx.x * BN;
    const int m0 = blockIdx.y * BM;

    // ---- stage loader: A|B, SW128-swizzled 128B rows
    auto load_stage = [&](int kk, int s){
        const uint32_t st = tb + (uint32_t)s * STAGE_BYTES;
        const int k0 = kk * BK;
        #pragma unroll
        for (int i = 0; i < 4; i++){                // A: 128 rows x 8 16B-chunks
            int idx = i * 256 + tid;
            int r = idx >> 3;
            int c8 = (idx & 7) * 8;                 // fp16 col
            uint32_t off = SWZ((uint32_t)(r * ROWB + c8 * 2));
            cp16(st + off, g_xh + (size_t)(m0 + r) * DIM + k0 + c8);
        }
        #pragma unroll
        for (int i = 0; i < 4; i++){                // B: 128 rows x 8 16B-chunks
            int idx = i * 256 + tid;
            int r = idx >> 3;
            int c8 = (idx & 7) * 8;
            uint32_t off = SWZ((uint32_t)(r * ROWB + c8 * 2));
            cp16(st + TILE_BYTES + off, g_wh + (size_t)(n0 + r) * DIM + k0 + c8);
        }
        CP_COMMIT();
    };

    float acc[4][4][4];
    #pragma unroll
    for (int a = 0; a < 4; a++)
        #pragma unroll
        for (int b = 0; b < 4; b++)
            #pragma unroll
            for (int c = 0; c < 4; c++) acc[a][b][c] = 0.0f;

    #pragma unroll
    for (int s = 0; s < NSTAGE-1; s++) load_stage(s, s);

    for (int kk = 0; kk < KITER; kk++){
        CP_WAIT(NSTAGE-2);
        __syncthreads();

        if (kk + NSTAGE-1 < KITER) load_stage(kk + NSTAGE-1, (kk + NSTAGE-1) % NSTAGE);
        else CP_COMMIT();   // empty group keeps wait_group accounting exact

        const uint32_t st = tb + (uint32_t)(kk % NSTAGE) * STAGE_BYTES;

        #pragma unroll
        for (int ks = 0; ks < 4; ks++){         // four k16 steps per BK=64
            uint32_t af[4][4], bf[2][4];
            #pragma unroll
            for (int mt = 0; mt < 4; mt++){
                int row = wm*64 + mt*16 + (lid & 15);
                uint32_t off = SWZ((uint32_t)(row * ROWB + ks*32 + ((lid >> 4) << 4)));
                ldsm4(af[mt], st + off);
            }
            #pragma unroll
            for (int nt = 0; nt < 2; nt++){     // each x4 covers 16 n-cols
                int row = wn*32 + nt*16 + (lid & 7) + ((lid >> 4) & 1) * 8;
                uint32_t off = SWZ((uint32_t)(row * ROWB + ks*32 + ((lid >> 3) & 1) * 16));
                ldsm4(bf[nt], st + TILE_BYTES + off);
            }
            #pragma unroll
            for (int mt = 0; mt < 4; mt++){
                #pragma unroll
                for (int ng = 0; ng < 4; ng++){
                    mma16816(acc[mt][ng], af[mt], &bf[ng >> 1][(ng & 1) * 2]);
                }
            }
        }
    }

    // ---- epilogue: bias + activation, fp16 stores (half2)
    const bool isgate = (n0 < DIM);
    const float* bias = isgate ? bg : bc;
    __half* outp = isgate ? g_gate : g_cand;
    const int nb = isgate ? n0 : (n0 - DIM);
    const int g = lid >> 2, t = lid & 3;

    #pragma unroll
    for (int mt = 0; mt < 4; mt++){
        #pragma unroll
        for (int ng = 0; ng < 4; ng++){
            int col = nb + wn*32 + ng*8 + t*2;
            float b0 = bias[col], b1 = bias[col + 1];
            int row0 = m0 + wm*64 + mt*16 + g;
            int row1 = row0 + 8;
            float v00 = acc[mt][ng][0] + b0, v01 = acc[mt][ng][1] + b1;
            float v10 = acc[mt][ng][2] + b0, v11 = acc[mt][ng][3] + b1;
            if (isgate){
                v00 = sigmoid_f(v00); v01 = sigmoid_f(v01);
                v10 = sigmoid_f(v10); v11 = sigmoid_f(v11);
            } else {
                v00 = tanh_f(v00); v01 = tanh_f(v01);
                v10 = tanh_f(v10); v11 = tanh_f(v11);
            }
            *reinterpret_cast<__half2*>(outp + (size_t)row0 * DIM + col) = __floats2half2_rn(v00, v01);
            *reinterpret_cast<__half2*>(outp + (size_t)row1 * DIM + col) = __floats2half2_rn(v10, v11);
        }
    }
}

// ============================================================================
// Kernels 4/5/6: chunked linear-recurrence scan  h_t = g_t*h_{t-1} + c_t
// Each thread handles 4 adjacent channels (8B fp16 loads).
// ============================================================================
__device__ __forceinline__ void load4h(float* f, const __half* p){
    uint2 u = *reinterpret_cast<const uint2*>(p);
    __half2 h0 = *reinterpret_cast<__half2*>(&u.x);
    __half2 h1 = *reinterpret_cast<__half2*>(&u.y);
    float2 a = __half22float2(h0), b = __half22float2(h1);
    f[0] = a.x; f[1] = a.y; f[2] = b.x; f[3] = b.y;
}

__global__ void scan_pass1(){
    int t = blockIdx.x * 256 + threadIdx.x;      // 262144 threads
    int d  = t & (DV - 1);                       // vec4 channel group
    int ch = (t >> 8) & (NCHK - 1);
    int b  = t >> 16;
    size_t base = ((size_t)b * SEQ + (size_t)ch * CH_T) * DIM + (size_t)d * 4;
    float A[4] = {1.f,1.f,1.f,1.f};
    float H[4] = {0.f,0.f,0.f,0.f};
    #pragma unroll 4
    for (int i = 0; i < CH_T; i++){
        float g[4], c[4];
        load4h(g, g_gate + base);
        load4h(c, g_cand + base);
        #pragma unroll
        for (int j = 0; j < 4; j++){
            A[j] *= g[j];
            H[j] = g[j]*H[j] + c[j];
        }
        base += DIM;
    }
    size_t sidx = ((size_t)b * NCHK + ch) * DV + d;
    reinterpret_cast<float4*>(g_Ast)[sidx] = make_float4(A[0],A[1],A[2],A[3]);
    reinterpret_cast<float4*>(g_Hst)[sidx] = make_float4(H[0],H[1],H[2],H[3]);
}

__global__ void scan_pass2(){
    int t = blockIdx.x * 256 + threadIdx.x;      // 1024 threads
    int d = t & (DV - 1);
    int b = t >> 8;
    float4 P = make_float4(0.f,0.f,0.f,0.f);
    #pragma unroll 4
    for (int k = 0; k < NCHK; k++){
        size_t s = ((size_t)b * NCHK + k) * DV + d;
        reinterpret_cast<float4*>(g_Pst)[s] = P;
        float4 A = reinterpret_cast<const float4*>(g_Ast)[s];
        float4 H = reinterpret_cast<const float4*>(g_Hst)[s];
        P.x = A.x*P.x + H.x; P.y = A.y*P.y + H.y;
        P.z = A.z*P.z + H.z; P.w = A.w*P.w + H.w;
    }
}

__global__ void scan_pass3(float* __restrict__ out){
    int t = blockIdx.x * 256 + threadIdx.x;      // 262144 threads
    int d  = t & (DV - 1);
    int ch = (t >> 8) & (NCHK - 1);
    int b  = t >> 16;
    size_t base = ((size_t)b * SEQ + (size_t)ch * CH_T) * DIM + (size_t)d * 4;
    size_t sidx = ((size_t)b * NCHK + ch) * DV + d;
    float4 hp = reinterpret_cast<const float4*>(g_Pst)[sidx];
    float h[4] = {hp.x, hp.y, hp.z, hp.w};
    #pragma unroll 4
    for (int i = 0; i < CH_T; i++){
        float g[4], c[4];
        load4h(g, g_gate + base);
        load4h(c, g_cand + base);
        #pragma unroll
        for (int j = 0; j < 4; j++)
            h[j] = g[j]*h[j] + c[j];
        *reinterpret_cast<float4*>(out + base) = make_float4(h[0],h[1],h[2],h[3]);
        base += DIM;
    }
}

// ============================================================================
// Launch
// ============================================================================
extern "C" void kernel_launch(void* const* d_in, const int* in_sizes, int n_in,
                              void* d_out, int out_size){
    (void)in_sizes; (void)n_in; (void)out_size;
    const float* x  = (const float*)d_in[0];
    const float* Wg = (const float*)d_in[1];
    const float* bg = (const float*)d_in[2];
    const float* Wc = (const float*)d_in[3];
    const float* bc = (const float*)d_in[4];
    float* out = (float*)d_out;

    cudaFuncSetAttribute(gemm_kernel, cudaFuncAttributeMaxDynamicSharedMemorySize, GEMM_SMEM);

    conv_x_kernel<<<(MTOT*(size_t)DIM)/4/256, 256>>>(x);              // my launch 0
    conv_w_kernel<<<(NTOT*(size_t)DIM)/4/256, 256>>>(Wg, Wc);         // my launch 1
    noop_kernel<<<1, 32>>>();                                         // my launch 2
    noop_kernel<<<1, 32>>>();                                         // my launch 3
    gemm_kernel<<<dim3(NTOT/BN, MTOT/BM), 256, GEMM_SMEM>>>(bg, bc);  // my launch 4 -> ncu skip-5 target
    scan_pass1<<<(BATCH*NCHK*DV)/256, 256>>>();                       // 1024 blocks
    scan_pass2<<<(BATCH*DV)/256, 256>>>();                            // 4 blocks
    scan_pass3<<<(BATCH*NCHK*DV)/256, 256>>>(out);                    // 1024 blocks
}

// round 9
// speedup vs baseline: 1.2083x; 1.0013x over previous
#include <cuda_runtime.h>
#include <cuda_fp16.h>
#include <cstdint>
#include <cstddef>

// ============================================================================
// Problem sizes
// ============================================================================
#define BATCH 4
#define SEQ   8192
#define DIM   1024
#define MTOT  (BATCH*SEQ)      // 32768 rows
#define NTOT  (2*DIM)          // 2048 combined output cols (gate | cand)
#define CH_T  32               // scan chunk length
#define NCHK  (SEQ/CH_T)       // 256 chunks per (b,d) channel
#define DV    (DIM/4)          // 256 vec4 channel groups

// ============================================================================
// Scratch (static device arrays — no allocation allowed)
// ============================================================================
__device__ __half g_xh[(size_t)MTOT*DIM];           // 64 MB
__device__ __half g_wh[(size_t)NTOT*DIM];           // 4 MB  (Wg rows 0..1023, Wc rows 1024..2047)
__device__ __half g_gate[(size_t)MTOT*DIM];         // 64 MB
__device__ __half g_cand[(size_t)MTOT*DIM];         // 64 MB
__device__ float g_Ast[(size_t)BATCH*NCHK*DIM];     // 4 MB
__device__ float g_Hst[(size_t)BATCH*NCHK*DIM];     // 4 MB
__device__ float g_Pst[(size_t)BATCH*NCHK*DIM];     // 4 MB

// ============================================================================
// Helpers (non-'a' PTX only: cp.async, ldmatrix, mma.sync)
// ============================================================================
__device__ __forceinline__ uint32_t smem_u32(const void* p){
    uint32_t a;
    asm("{ .reg .u64 t; cvta.to.shared.u64 t, %1; cvt.u32.u64 %0, t; }" : "=r"(a) : "l"(p));
    return a;
}
__device__ __forceinline__ void cp16(uint32_t smem_addr, const void* gptr){
    asm volatile("cp.async.cg.shared.global [%0], [%1], 16;"
                 :: "r"(smem_addr), "l"(__cvta_generic_to_global(gptr)) : "memory");
}
#define CP_COMMIT()  asm volatile("cp.async.commit_group;" ::: "memory")
#define CP_WAIT(n)   asm volatile("cp.async.wait_group %0;" :: "n"(n) : "memory")

__device__ __forceinline__ void ldsm4(uint32_t* r, uint32_t addr){
    asm volatile("ldmatrix.sync.aligned.m8n8.x4.shared.b16 {%0,%1,%2,%3}, [%4];"
                 : "=r"(r[0]),"=r"(r[1]),"=r"(r[2]),"=r"(r[3]) : "r"(addr));
}
__device__ __forceinline__ void mma16816(float* d, const uint32_t* a, const uint32_t* b){
    asm volatile("mma.sync.aligned.m16n8k16.row.col.f32.f16.f16.f32 "
                 "{%0,%1,%2,%3}, {%4,%5,%6,%7}, {%8,%9}, {%0,%1,%2,%3};"
                 : "+f"(d[0]),"+f"(d[1]),"+f"(d[2]),"+f"(d[3])
                 : "r"(a[0]),"r"(a[1]),"r"(a[2]),"r"(a[3]), "r"(b[0]),"r"(b[1]));
}

__device__ __forceinline__ float sigmoid_f(float v){
    return 1.0f / (1.0f + __expf(-v));
}
__device__ __forceinline__ float tanh_f(float v){
    float a = fabsf(v);
    float e = __expf(-2.0f * a);
    float t = (1.0f - e) / (1.0f + e);
    return copysignf(t, v);
}

// ============================================================================
// No-op kernel: with the harness's 2 pre-launches, one noop puts gemm_kernel
// at global launch index 5 = ncu's skip-5 capture target.
// ============================================================================
__global__ void noop_kernel(){}

// ============================================================================
// Kernel 1: convert x (fp32) -> fp16
// ============================================================================
__global__ void conv_x_kernel(const float* __restrict__ x){
    size_t i = ((size_t)blockIdx.x * blockDim.x + threadIdx.x) * 4;
    float4 v = *reinterpret_cast<const float4*>(x + i);
    __half2* ph = reinterpret_cast<__half2*>(g_xh + i);
    ph[0] = __floats2half2_rn(v.x, v.y);
    ph[1] = __floats2half2_rn(v.z, v.w);
}

// ============================================================================
// Kernel 2: convert [Wg;Wc] (fp32) -> fp16, concatenated rows
// ============================================================================
__global__ void conv_w_kernel(const float* __restrict__ Wg, const float* __restrict__ Wc){
    size_t i = ((size_t)blockIdx.x * blockDim.x + threadIdx.x) * 4;
    const size_t HALF = (size_t)DIM * DIM;
    float4 v = (i < HALF) ? *reinterpret_cast<const float4*>(Wg + i)
                          : *reinterpret_cast<const float4*>(Wc + (i - HALF));
    __half2* ph = reinterpret_cast<__half2*>(g_wh + i);
    ph[0] = __floats2half2_rn(v.x, v.y);
    ph[1] = __floats2half2_rn(v.z, v.w);
}

// ============================================================================
// Kernel 3: fused dual GEMM (mma.sync fp16, fp32 accum)
//   BM=128, BN=128, BK=64 (SW128 rows), 8 warps, warp tile 64x32, 2 CTA/SM
//   (byte-identical to the 545.4us R6 config — profiling target this round)
// ============================================================================
#define BM 128
#define BN 128
#define BK 64
#define NSTAGE 3
#define KITER (DIM/BK)              // 16
#define ROWB 128                    // bytes per smem row (64 halves)
#define TILE_BYTES (128*ROWB)       // 16384 per matrix per stage
#define STAGE_BYTES (2*TILE_BYTES)  // A|B = 32768
#define GEMM_SMEM (NSTAGE*STAGE_BYTES + 128)
#define SWZ(off) ((off) ^ (((off) >> 3) & 0x70))

__global__ void __launch_bounds__(256, 2)
gemm_kernel(const float* __restrict__ bg, const float* __restrict__ bc){
    extern __shared__ char smem[];
    const uint32_t tb = (smem_u32(smem) + 127u) & ~127u;   // 128B-aligned tile base
    const int tid = threadIdx.x;
    const int wid = tid >> 5;
    const int lid = tid & 31;
    const int wm = wid >> 2;           // 0..1  (64-row slabs)
    const int wn = wid & 3;            // 0..3  (32-col slabs)
    const int n0 = blockIdx.x * BN;
    const int m0 = blockIdx.y * BM;

    // ---- stage loader: A|B, SW128-swizzled 128B rows
    auto load_stage = [&](int kk, int s){
        const uint32_t st = tb + (uint32_t)s * STAGE_BYTES;
        const int k0 = kk * BK;
        #pragma unroll
        for (int i = 0; i < 4; i++){                // A: 128 rows x 8 16B-chunks
            int idx = i * 256 + tid;
            int r = idx >> 3;
            int c8 = (idx & 7) * 8;                 // fp16 col
            uint32_t off = SWZ((uint32_t)(r * ROWB + c8 * 2));
            cp16(st + off, g_xh + (size_t)(m0 + r) * DIM + k0 + c8);
        }
        #pragma unroll
        for (int i = 0; i < 4; i++){                // B: 128 rows x 8 16B-chunks
            int idx = i * 256 + tid;
            int r = idx >> 3;
            int c8 = (idx & 7) * 8;
            uint32_t off = SWZ((uint32_t)(r * ROWB + c8 * 2));
            cp16(st + TILE_BYTES + off, g_wh + (size_t)(n0 + r) * DIM + k0 + c8);
        }
        CP_COMMIT();
    };

    float acc[4][4][4];
    #pragma unroll
    for (int a = 0; a < 4; a++)
        #pragma unroll
        for (int b = 0; b < 4; b++)
            #pragma unroll
            for (int c = 0; c < 4; c++) acc[a][b][c] = 0.0f;

    #pragma unroll
    for (int s = 0; s < NSTAGE-1; s++) load_stage(s, s);

    for (int kk = 0; kk < KITER; kk++){
        CP_WAIT(NSTAGE-2);
        __syncthreads();

        if (kk + NSTAGE-1 < KITER) load_stage(kk + NSTAGE-1, (kk + NSTAGE-1) % NSTAGE);
        else CP_COMMIT();   // empty group keeps wait_group accounting exact

        const uint32_t st = tb + (uint32_t)(kk % NSTAGE) * STAGE_BYTES;

        #pragma unroll
        for (int ks = 0; ks < 4; ks++){         // four k16 steps per BK=64
            uint32_t af[4][4], bf[2][4];
            #pragma unroll
            for (int mt = 0; mt < 4; mt++){
                int row = wm*64 + mt*16 + (lid & 15);
                uint32_t off = SWZ((uint32_t)(row * ROWB + ks*32 + ((lid >> 4) << 4)));
                ldsm4(af[mt], st + off);
            }
            #pragma unroll
            for (int nt = 0; nt < 2; nt++){     // each x4 covers 16 n-cols
                int row = wn*32 + nt*16 + (lid & 7) + ((lid >> 4) & 1) * 8;
                uint32_t off = SWZ((uint32_t)(row * ROWB + ks*32 + ((lid >> 3) & 1) * 16));
                ldsm4(bf[nt], st + TILE_BYTES + off);
            }
            #pragma unroll
            for (int mt = 0; mt < 4; mt++){
                #pragma unroll
                for (int ng = 0; ng < 4; ng++){
                    mma16816(acc[mt][ng], af[mt], &bf[ng >> 1][(ng & 1) * 2]);
                }
            }
        }
    }

    // ---- epilogue: bias + activation, fp16 stores (half2)
    const bool isgate = (n0 < DIM);
    const float* bias = isgate ? bg : bc;
    __half* outp = isgate ? g_gate : g_cand;
    const int nb = isgate ? n0 : (n0 - DIM);
    const int g = lid >> 2, t = lid & 3;

    #pragma unroll
    for (int mt = 0; mt < 4; mt++){
        #pragma unroll
        for (int ng = 0; ng < 4; ng++){
            int col = nb + wn*32 + ng*8 + t*2;
            float b0 = bias[col], b1 = bias[col + 1];
            int row0 = m0 + wm*64 + mt*16 + g;
            int row1 = row0 + 8;
            float v00 = acc[mt][ng][0] + b0, v01 = acc[mt][ng][1] + b1;
            float v10 = acc[mt][ng][2] + b0, v11 = acc[mt][ng][3] + b1;
            if (isgate){
                v00 = sigmoid_f(v00); v01 = sigmoid_f(v01);
                v10 = sigmoid_f(v10); v11 = sigmoid_f(v11);
            } else {
                v00 = tanh_f(v00); v01 = tanh_f(v01);
                v10 = tanh_f(v10); v11 = tanh_f(v11);
            }
            *reinterpret_cast<__half2*>(outp + (size_t)row0 * DIM + col) = __floats2half2_rn(v00, v01);
            *reinterpret_cast<__half2*>(outp + (size_t)row1 * DIM + col) = __floats2half2_rn(v10, v11);
        }
    }
}

// ============================================================================
// Kernels 4/5/6: chunked linear-recurrence scan  h_t = g_t*h_{t-1} + c_t
// Each thread handles 4 adjacent channels (8B fp16 loads), unroll-8 for MLP.
// ============================================================================
__device__ __forceinline__ void load4h(float* f, const __half* p){
    uint2 u = *reinterpret_cast<const uint2*>(p);
    __half2 h0 = *reinterpret_cast<__half2*>(&u.x);
    __half2 h1 = *reinterpret_cast<__half2*>(&u.y);
    float2 a = __half22float2(h0), b = __half22float2(h1);
    f[0] = a.x; f[1] = a.y; f[2] = b.x; f[3] = b.y;
}

__global__ void scan_pass1(){
    int t = blockIdx.x * 256 + threadIdx.x;      // 262144 threads
    int d  = t & (DV - 1);                       // vec4 channel group
    int ch = (t >> 8) & (NCHK - 1);
    int b  = t >> 16;
    size_t base = ((size_t)b * SEQ + (size_t)ch * CH_T) * DIM + (size_t)d * 4;
    float A[4] = {1.f,1.f,1.f,1.f};
    float H[4] = {0.f,0.f,0.f,0.f};
    #pragma unroll 8
    for (int i = 0; i < CH_T; i++){
        float g[4], c[4];
        load4h(g, g_gate + base);
        load4h(c, g_cand + base);
        #pragma unroll
        for (int j = 0; j < 4; j++){
            A[j] *= g[j];
            H[j] = g[j]*H[j] + c[j];
        }
        base += DIM;
    }
    size_t sidx = ((size_t)b * NCHK + ch) * DV + d;
    reinterpret_cast<float4*>(g_Ast)[sidx] = make_float4(A[0],A[1],A[2],A[3]);
    reinterpret_cast<float4*>(g_Hst)[sidx] = make_float4(H[0],H[1],H[2],H[3]);
}

__global__ void scan_pass2(){
    int t = blockIdx.x * 256 + threadIdx.x;      // 1024 threads
    int d = t & (DV - 1);
    int b = t >> 8;
    float4 P = make_float4(0.f,0.f,0.f,0.f);
    #pragma unroll 4
    for (int k = 0; k < NCHK; k++){
        size_t s = ((size_t)b * NCHK + k) * DV + d;
        reinterpret_cast<float4*>(g_Pst)[s] = P;
        float4 A = reinterpret_cast<const float4*>(g_Ast)[s];
        float4 H = reinterpret_cast<const float4*>(g_Hst)[s];
        P.x = A.x*P.x + H.x; P.y = A.y*P.y + H.y;
        P.z = A.z*P.z + H.z; P.w = A.w*P.w + H.w;
    }
}

__global__ void scan_pass3(float* __restrict__ out){
    int t = blockIdx.x * 256 + threadIdx.x;      // 262144 threads
    int d  = t & (DV - 1);
    int ch = (t >> 8) & (NCHK - 1);
    int b  = t >> 16;
    size_t base = ((size_t)b * SEQ + (size_t)ch * CH_T) * DIM + (size_t)d * 4;
    size_t sidx = ((size_t)b * NCHK + ch) * DV + d;
    float4 hp = reinterpret_cast<const float4*>(g_Pst)[sidx];
    float h[4] = {hp.x, hp.y, hp.z, hp.w};
    #pragma unroll 8
    for (int i = 0; i < CH_T; i++){
        float g[4], c[4];
        load4h(g, g_gate + base);
        load4h(c, g_cand + base);
        #pragma unroll
        for (int j = 0; j < 4; j++)
            h[j] = g[j]*h[j] + c[j];
        *reinterpret_cast<float4*>(out + base) = make_float4(h[0],h[1],h[2],h[3]);
        base += DIM;
    }
}

// ============================================================================
// Launch
// ============================================================================
extern "C" void kernel_launch(void* const* d_in, const int* in_sizes, int n_in,
                              void* d_out, int out_size){
    (void)in_sizes; (void)n_in; (void)out_size;
    const float* x  = (const float*)d_in[0];
    const float* Wg = (const float*)d_in[1];
    const float* bg = (const float*)d_in[2];
    const float* Wc = (const float*)d_in[3];
    const float* bc = (const float*)d_in[4];
    float* out = (float*)d_out;

    cudaFuncSetAttribute(gemm_kernel, cudaFuncAttributeMaxDynamicSharedMemorySize, GEMM_SMEM);

    conv_x_kernel<<<(MTOT*(size_t)DIM)/4/256, 256>>>(x);              // my launch 0
    conv_w_kernel<<<(NTOT*(size_t)DIM)/4/256, 256>>>(Wg, Wc);         // my launch 1
    noop_kernel<<<1, 32>>>();                                         // my launch 2
    gemm_kernel<<<dim3(NTOT/BN, MTOT/BM), 256, GEMM_SMEM>>>(bg, bc);  // my launch 3 -> ncu target
    scan_pass1<<<(BATCH*NCHK*DV)/256, 256>>>();                       // 1024 blocks
    scan_pass2<<<(BATCH*DV)/256, 256>>>();                            // 4 blocks
    scan_pass3<<<(BATCH*NCHK*DV)/256, 256>>>(out);                    // 1024 blocks
}

// round 11
// speedup vs baseline: 1.2329x; 1.0204x over previous
#include <cuda_runtime.h>
#include <cuda_fp16.h>
#include <cstdint>
#include <cstddef>

// ============================================================================
// Problem sizes
// ============================================================================
#define BATCH 4
#define SEQ   8192
#define DIM   1024
#define MTOT  (BATCH*SEQ)      // 32768 rows
#define NTOT  (2*DIM)          // 2048 combined output cols (gate | cand)
#define CH_T  32               // scan chunk length
#define NCHK  (SEQ/CH_T)       // 256 chunks per (b,d) channel
#define DV    (DIM/4)          // 256 vec4 channel groups

// ============================================================================
// Scratch (static device arrays — no allocation allowed)
// ============================================================================
__device__ __half g_xh[(size_t)MTOT*DIM];           // 64 MB
__device__ __half g_wh[(size_t)NTOT*DIM];           // 4 MB  (Wg rows 0..1023, Wc rows 1024..2047)
__device__ __half g_gate[(size_t)MTOT*DIM];         // 64 MB
__device__ __half g_cand[(size_t)MTOT*DIM];         // 64 MB
__device__ float g_Ast[(size_t)BATCH*NCHK*DIM];     // 4 MB
__device__ float g_Hst[(size_t)BATCH*NCHK*DIM];     // 4 MB
__device__ float g_Pst[(size_t)BATCH*NCHK*DIM];     // 4 MB

// ============================================================================
// Helpers (non-'a' PTX only: cp.async, ldmatrix, mma.sync)
// ============================================================================
__device__ __forceinline__ uint32_t smem_u32(const void* p){
    uint32_t a;
    asm("{ .reg .u64 t; cvta.to.shared.u64 t, %1; cvt.u32.u64 %0, t; }" : "=r"(a) : "l"(p));
    return a;
}
__device__ __forceinline__ void cp16(uint32_t smem_addr, const void* gptr){
    asm volatile("cp.async.cg.shared.global [%0], [%1], 16;"
                 :: "r"(smem_addr), "l"(__cvta_generic_to_global(gptr)) : "memory");
}
#define CP_COMMIT()  asm volatile("cp.async.commit_group;" ::: "memory")
#define CP_WAIT(n)   asm volatile("cp.async.wait_group %0;" :: "n"(n) : "memory")

__device__ __forceinline__ void ldsm4(uint32_t* r, uint32_t addr){
    asm volatile("ldmatrix.sync.aligned.m8n8.x4.shared.b16 {%0,%1,%2,%3}, [%4];"
                 : "=r"(r[0]),"=r"(r[1]),"=r"(r[2]),"=r"(r[3]) : "r"(addr));
}
__device__ __forceinline__ void mma16816(float* d, const uint32_t* a, const uint32_t* b){
    asm volatile("mma.sync.aligned.m16n8k16.row.col.f32.f16.f16.f32 "
                 "{%0,%1,%2,%3}, {%4,%5,%6,%7}, {%8,%9}, {%0,%1,%2,%3};"
                 : "+f"(d[0]),"+f"(d[1]),"+f"(d[2]),"+f"(d[3])
                 : "r"(a[0]),"r"(a[1]),"r"(a[2]),"r"(a[3]), "r"(b[0]),"r"(b[1]));
}

__device__ __forceinline__ float sigmoid_f(float v){
    return 1.0f / (1.0f + __expf(-v));
}
__device__ __forceinline__ float tanh_f(float v){
    float a = fabsf(v);
    float e = __expf(-2.0f * a);
    float t = (1.0f - e) / (1.0f + e);
    return copysignf(t, v);
}

// ============================================================================
// No-op kernel: keeps gemm_kernel at ncu's skip-5 capture slot
// ============================================================================
__global__ void noop_kernel(){}

// ============================================================================
// Kernel 1: convert x (fp32) -> fp16
// ============================================================================
__global__ void conv_x_kernel(const float* __restrict__ x){
    size_t i = ((size_t)blockIdx.x * blockDim.x + threadIdx.x) * 4;
    float4 v = *reinterpret_cast<const float4*>(x + i);
    __half2* ph = reinterpret_cast<__half2*>(g_xh + i);
    ph[0] = __floats2half2_rn(v.x, v.y);
    ph[1] = __floats2half2_rn(v.z, v.w);
}

// ============================================================================
// Kernel 2: convert [Wg;Wc] (fp32) -> fp16, concatenated rows
// ============================================================================
__global__ void conv_w_kernel(const float* __restrict__ Wg, const float* __restrict__ Wc){
    size_t i = ((size_t)blockIdx.x * blockDim.x + threadIdx.x) * 4;
    const size_t HALF = (size_t)DIM * DIM;
    float4 v = (i < HALF) ? *reinterpret_cast<const float4*>(Wg + i)
                          : *reinterpret_cast<const float4*>(Wc + (i - HALF));
    __half2* ph = reinterpret_cast<__half2*>(g_wh + i);
    ph[0] = __floats2half2_rn(v.x, v.y);
    ph[1] = __floats2half2_rn(v.z, v.w);
}

// ============================================================================
// Kernel 3: fused dual GEMM (mma.sync fp16, fp32 accum)
//   BM=128, BN=128, BK=64 (SW128 rows), 8 warps, warp tile 64x32, 2 CTA/SM
//   Address-hoisted mainloop; per-ks step applied via XOR (swizzle-safe):
//   SWZ(x + ks*32) == SWZ(x) ^ (ks*32)  when x has bits 5-6 clear.
// ============================================================================
#define BM 128
#define BN 128
#define BK 64
#define NSTAGE 3
#define KITER (DIM/BK)              // 16
#define ROWB 128                    // bytes per smem row (64 halves)
#define TILE_BYTES (128*ROWB)       // 16384 per matrix per stage
#define STAGE_BYTES (2*TILE_BYTES)  // A|B = 32768
#define GEMM_SMEM (NSTAGE*STAGE_BYTES + 128)
#define SWZ(off) ((off) ^ (((off) >> 3) & 0x70))

__global__ void __launch_bounds__(256, 2)
gemm_kernel(const float* __restrict__ bg, const float* __restrict__ bc){
    extern __shared__ char smem[];
    const uint32_t tb = (smem_u32(smem) + 127u) & ~127u;   // 128B-aligned tile base
    const int tid = threadIdx.x;
    const int wid = tid >> 5;
    const int lid = tid & 31;
    const int wm = wid >> 2;           // 0..1  (64-row slabs)
    const int wn = wid & 3;            // 0..3  (32-col slabs)
    const int n0 = blockIdx.x * BN;
    const int m0 = blockIdx.y * BM;

    // ---- thread-constant addressing (hoisted out of all loops) ----
    // Store side: each thread writes 4 16B chunks per tile; chunk i at +i*4096
    // (bit 12; below-swizzle-window low bits < 4096, so plain add is safe).
    const int tr  = tid >> 3;               // smem row 0..31 (+i*32)
    const int tc8 = (tid & 7) * 8;          // fp16 col of 16B chunk
    const uint32_t swzStore = SWZ((uint32_t)(tr * ROWB + tc8 * 2));
    const size_t baseA = (size_t)(m0 + tr) * DIM + tc8;
    const size_t baseB = (size_t)(n0 + tr) * DIM + tc8;

    // Fragment side: 6 swizzled base offsets (unswizzled x has bits 5-6 clear,
    // so the ks*32 advance is applied with XOR on the swizzled value).
    uint32_t offA[4], offB[2];
    #pragma unroll
    for (int mt = 0; mt < 4; mt++){
        int row = wm*64 + mt*16 + (lid & 15);
        offA[mt] = SWZ((uint32_t)(row * ROWB + ((lid >> 4) << 4)));
    }
    #pragma unroll
    for (int nt = 0; nt < 2; nt++){
        int row = wn*32 + nt*16 + (lid & 7) + ((lid >> 4) & 1) * 8;
        offB[nt] = SWZ((uint32_t)(row * ROWB + ((lid >> 3) & 1) * 16)) + TILE_BYTES;
    }

    auto load_stage = [&](int kk, int s){
        const uint32_t st = tb + (uint32_t)s * STAGE_BYTES + swzStore;
        const int k0 = kk * BK;
        #pragma unroll
        for (int i = 0; i < 4; i++)
            cp16(st + i*4096, g_xh + baseA + (size_t)(i*32)*DIM + k0);
        #pragma unroll
        for (int i = 0; i < 4; i++)
            cp16(st + TILE_BYTES + i*4096, g_wh + baseB + (size_t)(i*32)*DIM + k0);
        CP_COMMIT();
    };

    float acc[4][4][4];
    #pragma unroll
    for (int a = 0; a < 4; a++)
        #pragma unroll
        for (int b = 0; b < 4; b++)
            #pragma unroll
            for (int c = 0; c < 4; c++) acc[a][b][c] = 0.0f;

    #pragma unroll
    for (int s = 0; s < NSTAGE-1; s++) load_stage(s, s);

    for (int kk = 0; kk < KITER; kk++){
        CP_WAIT(NSTAGE-2);
        __syncthreads();

        if (kk + NSTAGE-1 < KITER) load_stage(kk + NSTAGE-1, (kk + NSTAGE-1) % NSTAGE);
        else CP_COMMIT();   // empty group keeps wait_group accounting exact

        const uint32_t st = tb + (uint32_t)(kk % NSTAGE) * STAGE_BYTES;

        #pragma unroll
        for (int ks = 0; ks < 4; ks++){         // four k16 steps per BK=64
            const uint32_t kx = (uint32_t)(ks * 32);
            uint32_t af[4][4], bf[2][4];
            #pragma unroll
            for (int mt = 0; mt < 4; mt++)
                ldsm4(af[mt], st + (offA[mt] ^ kx));
            #pragma unroll
            for (int nt = 0; nt < 2; nt++)
                ldsm4(bf[nt], st + (offB[nt] ^ kx));
            #pragma unroll
            for (int mt = 0; mt < 4; mt++){
                #pragma unroll
                for (int ng = 0; ng < 4; ng++){
                    mma16816(acc[mt][ng], af[mt], &bf[ng >> 1][(ng & 1) * 2]);
                }
            }
        }
    }

    // ---- epilogue: bias + activation, fp16 stores (half2)
    const bool isgate = (n0 < DIM);
    const float* bias = isgate ? bg : bc;
    __half* outp = isgate ? g_gate : g_cand;
    const int nb = isgate ? n0 : (n0 - DIM);
    const int g = lid >> 2, t = lid & 3;

    #pragma unroll
    for (int mt = 0; mt < 4; mt++){
        #pragma unroll
        for (int ng = 0; ng < 4; ng++){
            int col = nb + wn*32 + ng*8 + t*2;
            float b0 = bias[col], b1 = bias[col + 1];
            int row0 = m0 + wm*64 + mt*16 + g;
            int row1 = row0 + 8;
            float v00 = acc[mt][ng][0] + b0, v01 = acc[mt][ng][1] + b1;
            float v10 = acc[mt][ng][2] + b0, v11 = acc[mt][ng][3] + b1;
            if (isgate){
                v00 = sigmoid_f(v00); v01 = sigmoid_f(v01);
                v10 = sigmoid_f(v10); v11 = sigmoid_f(v11);
            } else {
                v00 = tanh_f(v00); v01 = tanh_f(v01);
                v10 = tanh_f(v10); v11 = tanh_f(v11);
            }
            *reinterpret_cast<__half2*>(outp + (size_t)row0 * DIM + col) = __floats2half2_rn(v00, v01);
            *reinterpret_cast<__half2*>(outp + (size_t)row1 * DIM + col) = __floats2half2_rn(v10, v11);
        }
    }
}

// ============================================================================
// Kernels 4/5/6: chunked linear-recurrence scan  h_t = g_t*h_{t-1} + c_t
// Each thread handles 4 adjacent channels (8B fp16 loads), unroll-8 for MLP.
// ============================================================================
__device__ __forceinline__ void load4h(float* f, const __half* p){
    uint2 u = *reinterpret_cast<const uint2*>(p);
    __half2 h0 = *reinterpret_cast<__half2*>(&u.x);
    __half2 h1 = *reinterpret_cast<__half2*>(&u.y);
    float2 a = __half22float2(h0), b = __half22float2(h1);
    f[0] = a.x; f[1] = a.y; f[2] = b.x; f[3] = b.y;
}

__global__ void scan_pass1(){
    int t = blockIdx.x * 256 + threadIdx.x;      // 262144 threads
    int d  = t & (DV - 1);                       // vec4 channel group
    int ch = (t >> 8) & (NCHK - 1);
    int b  = t >> 16;
    size_t base = ((size_t)b * SEQ + (size_t)ch * CH_T) * DIM + (size_t)d * 4;
    float A[4] = {1.f,1.f,1.f,1.f};
    float H[4] = {0.f,0.f,0.f,0.f};
    #pragma unroll 8
    for (int i = 0; i < CH_T; i++){
        float g[4], c[4];
        load4h(g, g_gate + base);
        load4h(c, g_cand + base);
        #pragma unroll
        for (int j = 0; j < 4; j++){
            A[j] *= g[j];
            H[j] = g[j]*H[j] + c[j];
        }
        base += DIM;
    }
    size_t sidx = ((size_t)b * NCHK + ch) * DV + d;
    reinterpret_cast<float4*>(g_Ast)[sidx] = make_float4(A[0],A[1],A[2],A[3]);
    reinterpret_cast<float4*>(g_Hst)[sidx] = make_float4(H[0],H[1],H[2],H[3]);
}

__global__ void scan_pass2(){
    int t = blockIdx.x * 256 + threadIdx.x;      // 1024 threads
    int d = t & (DV - 1);
    int b = t >> 8;
    float4 P = make_float4(0.f,0.f,0.f,0.f);
    #pragma unroll 4
    for (int k = 0; k < NCHK; k++){
        size_t s = ((size_t)b * NCHK + k) * DV + d;
        reinterpret_cast<float4*>(g_Pst)[s] = P;
        float4 A = reinterpret_cast<const float4*>(g_Ast)[s];
        float4 H = reinterpret_cast<const float4*>(g_Hst)[s];
        P.x = A.x*P.x + H.x; P.y = A.y*P.y + H.y;
        P.z = A.z*P.z + H.z; P.w = A.w*P.w + H.w;
    }
}

__global__ void scan_pass3(float* __restrict__ out){
    int t = blockIdx.x * 256 + threadIdx.x;      // 262144 threads
    int d  = t & (DV - 1);
    int ch = (t >> 8) & (NCHK - 1);
    int b  = t >> 16;
    size_t base = ((size_t)b * SEQ + (size_t)ch * CH_T) * DIM + (size_t)d * 4;
    size_t sidx = ((size_t)b * NCHK + ch) * DV + d;
    float4 hp = reinterpret_cast<const float4*>(g_Pst)[sidx];
    float h[4] = {hp.x, hp.y, hp.z, hp.w};
    #pragma unroll 8
    for (int i = 0; i < CH_T; i++){
        float g[4], c[4];
        load4h(g, g_gate + base);
        load4h(c, g_cand + base);
        #pragma unroll
        for (int j = 0; j < 4; j++)
            h[j] = g[j]*h[j] + c[j];
        *reinterpret_cast<float4*>(out + base) = make_float4(h[0],h[1],h[2],h[3]);
        base += DIM;
    }
}

// ============================================================================
// Launch
// ============================================================================
extern "C" void kernel_launch(void* const* d_in, const int* in_sizes, int n_in,
                              void* d_out, int out_size){
    (void)in_sizes; (void)n_in; (void)out_size;
    const float* x  = (const float*)d_in[0];
    const float* Wg = (const float*)d_in[1];
    const float* bg = (const float*)d_in[2];
    const float* Wc = (const float*)d_in[3];
    const float* bc = (const float*)d_in[4];
    float* out = (float*)d_out;

    cudaFuncSetAttribute(gemm_kernel, cudaFuncAttributeMaxDynamicSharedMemorySize, GEMM_SMEM);

    conv_x_kernel<<<(MTOT*(size_t)DIM)/4/256, 256>>>(x);              // my launch 0
    conv_w_kernel<<<(NTOT*(size_t)DIM)/4/256, 256>>>(Wg, Wc);         // my launch 1
    noop_kernel<<<1, 32>>>();                                         // my launch 2
    gemm_kernel<<<dim3(NTOT/BN, MTOT/BM), 256, GEMM_SMEM>>>(bg, bc);  // my launch 3 -> ncu target
    scan_pass1<<<(BATCH*NCHK*DV)/256, 256>>>();                       // 1024 blocks
    scan_pass2<<<(BATCH*DV)/256, 256>>>();                            // 4 blocks
    scan_pass3<<<(BATCH*NCHK*DV)/256, 256>>>(out);                    // 1024 blocks
}